// round 1
// baseline (speedup 1.0000x reference)
#include <cuda_runtime.h>
#include <math.h>

#define TOKENS 262144      // 4 * 256 * 256
#define CDIM   192
#define QKVN   576
#define NHEADS 6
#define NWINS  4096        // 4 * 32 * 32

// Scratch (allocation-free rule: __device__ globals)
__device__ float g_qkv[(size_t)TOKENS * QKVN];   // [token][576] : q|k|v, each [head][32]
__device__ float g_att[(size_t)TOKENS * CDIM];   // attention output, [token][192]

// C[m][n] = sum_k A[m][k] * W[n][k] + bias[n]
// BM=128, BN=64, BK=32, 256 threads, 8x4 microtile
template<int N>
__global__ __launch_bounds__(256) void gemm_bias(
    const float* __restrict__ A, const float* __restrict__ W,
    const float* __restrict__ bias, float* __restrict__ C)
{
    __shared__ float As[32][129];   // [k][m], pad -> conflict-free stores & loads
    __shared__ float Bs[32][65];    // [k][n]
    const int bm = blockIdx.y * 128;
    const int bn = blockIdx.x * 64;
    const int t  = threadIdx.x;
    const int tx = t & 15;          // 16 col groups * 4
    const int ty = t >> 4;          // 16 row groups * 8
    const int lcol = t & 31;
    const int lrow = t >> 5;        // 0..7

    float acc[8][4];
#pragma unroll
    for (int i = 0; i < 8; ++i)
#pragma unroll
        for (int j = 0; j < 4; ++j) acc[i][j] = 0.f;

    for (int k0 = 0; k0 < CDIM; k0 += 32) {
#pragma unroll
        for (int p = 0; p < 16; ++p) {
            int r = lrow + p * 8;
            As[lcol][r] = A[(bm + r) * CDIM + k0 + lcol];
        }
#pragma unroll
        for (int p = 0; p < 8; ++p) {
            int r = lrow + p * 8;
            Bs[lcol][r] = W[(bn + r) * CDIM + k0 + lcol];
        }
        __syncthreads();
#pragma unroll
        for (int kk = 0; kk < 32; ++kk) {
            float a[8], b[4];
#pragma unroll
            for (int i = 0; i < 8; ++i) a[i] = As[kk][ty * 8 + i];
#pragma unroll
            for (int j = 0; j < 4; ++j) b[j] = Bs[kk][tx * 4 + j];
#pragma unroll
            for (int i = 0; i < 8; ++i)
#pragma unroll
                for (int j = 0; j < 4; ++j) acc[i][j] += a[i] * b[j];
        }
        __syncthreads();
    }
#pragma unroll
    for (int i = 0; i < 8; ++i) {
        int m = bm + ty * 8 + i;
#pragma unroll
        for (int j = 0; j < 4; ++j) {
            int n = bn + tx * 4 + j;
            C[m * N + n] = acc[i][j] + __ldg(&bias[n]);
        }
    }
}

// One block per (window, head). 64 tokens, hd=32.
__global__ __launch_bounds__(256) void win_attn(const float* __restrict__ bias)
{
    __shared__ float q[64][33];                     // [pos][d]
    __shared__ __align__(16) float kT[32][68];      // [d][pos], float4-loadable
    __shared__ __align__(16) float v[64][34];       // [pos][d], float2-loadable
    __shared__ float S[64][65];

    const int head = blockIdx.x % NHEADS;
    const int win  = blockIdx.x / NHEADS;
    const int b  = win >> 10;
    const int wy = (win >> 5) & 31;
    const int wx = win & 31;
    const int t = threadIdx.x;
    const float scale = 0.17677669529663687f;       // 1/sqrt(32)

    // Gather q, k, v for this (window, head). Per-row 128B contiguous -> coalesced.
    for (int idx = t; idx < 64 * 32; idx += 256) {
        int p = idx >> 5;
        int d = idx & 31;
        int h = wy * 8 + (p >> 3);
        int w = wx * 8 + (p & 7);
        int tok = b * 65536 + h * 256 + w;
        const float* base = g_qkv + tok * QKVN + head * 32 + d;
        q[p][d]  = base[0] * scale;
        kT[d][p] = base[CDIM];
        v[p][d]  = base[2 * CDIM];
    }
    __syncthreads();

    // S = (q*scale) @ k^T + bias[head]   (64x64, 4x4 register tile per thread)
    {
        const int ti = t >> 4;
        const int tj = t & 15;
        float acc[4][4];
#pragma unroll
        for (int i = 0; i < 4; ++i)
#pragma unroll
            for (int j = 0; j < 4; ++j) acc[i][j] = 0.f;
#pragma unroll
        for (int kk = 0; kk < 32; ++kk) {
            float a[4];
#pragma unroll
            for (int i = 0; i < 4; ++i) a[i] = q[ti * 4 + i][kk];
            float4 b4 = *(const float4*)&kT[kk][tj * 4];
            float bb[4] = {b4.x, b4.y, b4.z, b4.w};
#pragma unroll
            for (int i = 0; i < 4; ++i)
#pragma unroll
                for (int j = 0; j < 4; ++j) acc[i][j] += a[i] * bb[j];
        }
        const float* bp = bias + head * 4096;
#pragma unroll
        for (int i = 0; i < 4; ++i)
#pragma unroll
            for (int j = 0; j < 4; ++j)
                S[ti * 4 + i][tj * 4 + j] = acc[i][j] + __ldg(&bp[(ti * 4 + i) * 64 + tj * 4 + j]);
    }
    __syncthreads();

    // Row softmax (one thread per row; strided addresses conflict-free via pad 65)
    if (t < 64) {
        float mx = -1e30f;
        for (int j = 0; j < 64; ++j) mx = fmaxf(mx, S[t][j]);
        float sum = 0.f;
        for (int j = 0; j < 64; ++j) {
            float e = expf(S[t][j] - mx);
            S[t][j] = e;
            sum += e;
        }
        float inv = 1.f / sum;
        for (int j = 0; j < 64; ++j) S[t][j] *= inv;
    }
    __syncthreads();

    // out = P @ v  (64x32), 4x2 register tile per thread
    {
        const int rg = t >> 4;   // 16 groups * 4 rows
        const int dg = t & 15;   // 16 groups * 2 d
        float o[4][2];
#pragma unroll
        for (int i = 0; i < 4; ++i) { o[i][0] = 0.f; o[i][1] = 0.f; }
        for (int j = 0; j < 64; ++j) {
            float2 vv = *(const float2*)&v[j][dg * 2];
#pragma unroll
            for (int i = 0; i < 4; ++i) {
                float pp = S[rg * 4 + i][j];
                o[i][0] += pp * vv.x;
                o[i][1] += pp * vv.y;
            }
        }
#pragma unroll
        for (int i = 0; i < 4; ++i) {
            int p = rg * 4 + i;
            int h = wy * 8 + (p >> 3);
            int w = wx * 8 + (p & 7);
            int tok = b * 65536 + h * 256 + w;
            float* dst = g_att + tok * CDIM + head * 32 + dg * 2;
            dst[0] = o[i][0];
            dst[1] = o[i][1];
        }
    }
}

extern "C" void kernel_launch(void* const* d_in, const int* in_sizes, int n_in,
                              void* d_out, int out_size)
{
    const float* x      = (const float*)d_in[0];
    const float* qkv_w  = (const float*)d_in[1];
    const float* qkv_b  = (const float*)d_in[2];
    const float* proj_w = (const float*)d_in[3];
    const float* proj_b = (const float*)d_in[4];
    const float* bias   = (const float*)d_in[5];
    float* out = (float*)d_out;

    float *qkv_p = nullptr, *att_p = nullptr;
    cudaGetSymbolAddress((void**)&qkv_p, g_qkv);
    cudaGetSymbolAddress((void**)&att_p, g_att);

    // 1) QKV GEMM: [262144,192] x [576,192]^T + b -> g_qkv
    dim3 g1(QKVN / 64, TOKENS / 128);
    gemm_bias<QKVN><<<g1, 256>>>(x, qkv_w, qkv_b, qkv_p);

    // 2) Windowed attention per (window, head)
    win_attn<<<NWINS * NHEADS, 256>>>(bias);

    // 3) Proj GEMM: [262144,192] x [192,192]^T + b -> out
    dim3 g3(CDIM / 64, TOKENS / 128);
    gemm_bias<CDIM><<<g3, 256>>>(att_p, proj_w, proj_b, out);
}

// round 3
// speedup vs baseline: 1.9138x; 1.9138x over previous
#include <cuda_runtime.h>
#include <cstdint>
#include <math.h>

#define TOKENS 262144      // 4 * 256 * 256
#define CDIM   192
#define QKVN   576
#define NHEADS 6
#define NWINS  4096

__device__ float g_qkv[(size_t)TOKENS * QKVN];
__device__ float g_att[(size_t)TOKENS * CDIM];

__device__ __forceinline__ float to_tf32(float x) {
    asm("cvt.rna.tf32.f32 %0, %1;" : "=f"(x) : "f"(x));
    return x;
}
__device__ __forceinline__ void mma_tf32(float* c, const uint32_t* a, const uint32_t* b) {
    asm volatile(
        "mma.sync.aligned.m16n8k8.row.col.f32.tf32.tf32.f32 "
        "{%0,%1,%2,%3}, {%4,%5,%6,%7}, {%8,%9}, {%0,%1,%2,%3};"
        : "+f"(c[0]), "+f"(c[1]), "+f"(c[2]), "+f"(c[3])
        : "r"(a[0]), "r"(a[1]), "r"(a[2]), "r"(a[3]), "r"(b[0]), "r"(b[1]));
}

// ---------------- warp-mma tf32 GEMM ----------------
// C[m][n] = sum_k A[m][k]*W[n][k] + bias[n]
// Block 128x96, 8 warps (4m x 2n), warp tile 32x48, BK=32, K=192.
template<int NOUT>
__global__ __launch_bounds__(256) void gemm_mma(
    const float* __restrict__ A, const float* __restrict__ W,
    const float* __restrict__ bias, float* __restrict__ C)
{
    __shared__ __align__(16) float As[128][36];
    __shared__ __align__(16) float Bs[96][36];

    const int t    = threadIdx.x;
    const int wid  = t >> 5;
    const int lane = t & 31;
    const int bm   = blockIdx.y * 128;
    const int bn   = blockIdx.x * 96;
    const int m0   = (wid >> 1) * 32;     // warp m offset in tile
    const int n0   = (wid & 1) * 48;      // warp n offset in tile

    const int gr = lane >> 2;             // lane/4: fragment row group
    const int gc = lane & 3;              // lane%4: fragment col group

    float acc[2][6][4];
#pragma unroll
    for (int i = 0; i < 2; ++i)
#pragma unroll
        for (int j = 0; j < 6; ++j)
#pragma unroll
            for (int r = 0; r < 4; ++r) acc[i][j][r] = 0.f;

    for (int k0 = 0; k0 < CDIM; k0 += 32) {
        // stage A: 128 rows x 8 float4
#pragma unroll
        for (int p = 0; p < 4; ++p) {
            int ci = t + p * 256;
            int r = ci >> 3, c = ci & 7;
            float4 v = __ldg((const float4*)(A + (size_t)(bm + r) * CDIM + k0 + c * 4));
            v.x = to_tf32(v.x); v.y = to_tf32(v.y); v.z = to_tf32(v.z); v.w = to_tf32(v.w);
            *(float4*)&As[r][c * 4] = v;
        }
        // stage B: 96 rows x 8 float4
#pragma unroll
        for (int p = 0; p < 3; ++p) {
            int ci = t + p * 256;
            int r = ci >> 3, c = ci & 7;
            float4 v = __ldg((const float4*)(W + (size_t)(bn + r) * CDIM + k0 + c * 4));
            v.x = to_tf32(v.x); v.y = to_tf32(v.y); v.z = to_tf32(v.z); v.w = to_tf32(v.w);
            *(float4*)&Bs[r][c * 4] = v;
        }
        __syncthreads();

#pragma unroll
        for (int ks = 0; ks < 4; ++ks) {
            const int kk = ks * 8;
            uint32_t af[2][4], bf[6][2];
#pragma unroll
            for (int mi = 0; mi < 2; ++mi) {
                int rb = m0 + mi * 16 + gr;
                af[mi][0] = __float_as_uint(As[rb    ][kk + gc    ]);
                af[mi][1] = __float_as_uint(As[rb + 8][kk + gc    ]);
                af[mi][2] = __float_as_uint(As[rb    ][kk + gc + 4]);
                af[mi][3] = __float_as_uint(As[rb + 8][kk + gc + 4]);
            }
#pragma unroll
            for (int ni = 0; ni < 6; ++ni) {
                int nb = n0 + ni * 8 + gr;
                bf[ni][0] = __float_as_uint(Bs[nb][kk + gc    ]);
                bf[ni][1] = __float_as_uint(Bs[nb][kk + gc + 4]);
            }
#pragma unroll
            for (int mi = 0; mi < 2; ++mi)
#pragma unroll
                for (int ni = 0; ni < 6; ++ni)
                    mma_tf32(acc[mi][ni], af[mi], bf[ni]);
        }
        __syncthreads();
    }

    // epilogue: c0,c1 at (row=gr, col=2*gc), c2,c3 at row+8
#pragma unroll
    for (int mi = 0; mi < 2; ++mi) {
        int mr = bm + m0 + mi * 16 + gr;
#pragma unroll
        for (int ni = 0; ni < 6; ++ni) {
            int nc = bn + n0 + ni * 8 + gc * 2;
            float2 bv = __ldg((const float2*)(bias + nc));
            float2 o0 = {acc[mi][ni][0] + bv.x, acc[mi][ni][1] + bv.y};
            float2 o1 = {acc[mi][ni][2] + bv.x, acc[mi][ni][3] + bv.y};
            *(float2*)(C + (size_t)mr * NOUT + nc)       = o0;
            *(float2*)(C + (size_t)(mr + 8) * NOUT + nc) = o1;
        }
    }
}

// ---------------- window attention (unchanged) ----------------
__global__ __launch_bounds__(256) void win_attn(const float* __restrict__ bias)
{
    __shared__ float q[64][33];
    __shared__ __align__(16) float kT[32][68];
    __shared__ __align__(16) float v[64][34];
    __shared__ float S[64][65];

    const int head = blockIdx.x % NHEADS;
    const int win  = blockIdx.x / NHEADS;
    const int b  = win >> 10;
    const int wy = (win >> 5) & 31;
    const int wx = win & 31;
    const int t = threadIdx.x;
    const float scale = 0.17677669529663687f;

    for (int idx = t; idx < 64 * 32; idx += 256) {
        int p = idx >> 5;
        int d = idx & 31;
        int h = wy * 8 + (p >> 3);
        int w = wx * 8 + (p & 7);
        int tok = b * 65536 + h * 256 + w;
        const float* base = g_qkv + (size_t)tok * QKVN + head * 32 + d;
        q[p][d]  = base[0] * scale;
        kT[d][p] = base[CDIM];
        v[p][d]  = base[2 * CDIM];
    }
    __syncthreads();

    {
        const int ti = t >> 4;
        const int tj = t & 15;
        float acc[4][4];
#pragma unroll
        for (int i = 0; i < 4; ++i)
#pragma unroll
            for (int j = 0; j < 4; ++j) acc[i][j] = 0.f;
#pragma unroll
        for (int kk = 0; kk < 32; ++kk) {
            float a[4];
#pragma unroll
            for (int i = 0; i < 4; ++i) a[i] = q[ti * 4 + i][kk];
            float4 b4 = *(const float4*)&kT[kk][tj * 4];
            float bb[4] = {b4.x, b4.y, b4.z, b4.w};
#pragma unroll
            for (int i = 0; i < 4; ++i)
#pragma unroll
                for (int j = 0; j < 4; ++j) acc[i][j] += a[i] * bb[j];
        }
        const float* bp = bias + head * 4096;
#pragma unroll
        for (int i = 0; i < 4; ++i)
#pragma unroll
            for (int j = 0; j < 4; ++j)
                S[ti * 4 + i][tj * 4 + j] = acc[i][j] + __ldg(&bp[(ti * 4 + i) * 64 + tj * 4 + j]);
    }
    __syncthreads();

    if (t < 64) {
        float mx = -1e30f;
        for (int j = 0; j < 64; ++j) mx = fmaxf(mx, S[t][j]);
        float sum = 0.f;
        for (int j = 0; j < 64; ++j) {
            float e = expf(S[t][j] - mx);
            S[t][j] = e;
            sum += e;
        }
        float inv = 1.f / sum;
        for (int j = 0; j < 64; ++j) S[t][j] *= inv;
    }
    __syncthreads();

    {
        const int rg = t >> 4;
        const int dg = t & 15;
        float o[4][2];
#pragma unroll
        for (int i = 0; i < 4; ++i) { o[i][0] = 0.f; o[i][1] = 0.f; }
        for (int j = 0; j < 64; ++j) {
            float2 vv = *(const float2*)&v[j][dg * 2];
#pragma unroll
            for (int i = 0; i < 4; ++i) {
                float pp = S[rg * 4 + i][j];
                o[i][0] += pp * vv.x;
                o[i][1] += pp * vv.y;
            }
        }
#pragma unroll
        for (int i = 0; i < 4; ++i) {
            int p = rg * 4 + i;
            int h = wy * 8 + (p >> 3);
            int w = wx * 8 + (p & 7);
            int tok = b * 65536 + h * 256 + w;
            float* dst = g_att + (size_t)tok * CDIM + head * 32 + dg * 2;
            dst[0] = o[i][0];
            dst[1] = o[i][1];
        }
    }
}

extern "C" void kernel_launch(void* const* d_in, const int* in_sizes, int n_in,
                              void* d_out, int out_size)
{
    const float* x      = (const float*)d_in[0];
    const float* qkv_w  = (const float*)d_in[1];
    const float* qkv_b  = (const float*)d_in[2];
    const float* proj_w = (const float*)d_in[3];
    const float* proj_b = (const float*)d_in[4];
    const float* bias   = (const float*)d_in[5];
    float* out = (float*)d_out;

    float *qkv_p = nullptr, *att_p = nullptr;
    cudaGetSymbolAddress((void**)&qkv_p, g_qkv);
    cudaGetSymbolAddress((void**)&att_p, g_att);

    // 1) QKV GEMM: [262144,192] x [576,192]^T + b
    dim3 g1(QKVN / 96, TOKENS / 128);
    gemm_mma<QKVN><<<g1, 256>>>(x, qkv_w, qkv_b, qkv_p);

    // 2) Windowed attention
    win_attn<<<NWINS * NHEADS, 256>>>(bias);

    // 3) Proj GEMM: [262144,192] x [192,192]^T + b
    dim3 g3(CDIM / 96, TOKENS / 128);
    gemm_mma<CDIM><<<g3, 256>>>(att_p, proj_w, proj_b, out);
}

// round 4
// speedup vs baseline: 3.1280x; 1.6344x over previous
#include <cuda_runtime.h>
#include <cstdint>
#include <math.h>

#define TOKENS 262144      // 4 * 256 * 256
#define CDIM   192
#define QKVN   576
#define NHEADS 6
#define NWINS  4096

__device__ float g_qkv[(size_t)TOKENS * QKVN];
__device__ float g_att[(size_t)TOKENS * CDIM];

__device__ __forceinline__ uint32_t smem_u32(const void* p) {
    uint32_t a;
    asm("{ .reg .u64 t; cvta.to.shared.u64 t, %1; cvt.u32.u64 %0, t; }" : "=r"(a) : "l"(p));
    return a;
}
__device__ __forceinline__ float to_tf32(float x) {
    asm("cvt.rna.tf32.f32 %0, %1;" : "=f"(x) : "f"(x));
    return x;
}
__device__ __forceinline__ void mma_tf32(float* c, const uint32_t* a, const uint32_t* b) {
    asm volatile(
        "mma.sync.aligned.m16n8k8.row.col.f32.tf32.tf32.f32 "
        "{%0,%1,%2,%3}, {%4,%5,%6,%7}, {%8,%9}, {%0,%1,%2,%3};"
        : "+f"(c[0]), "+f"(c[1]), "+f"(c[2]), "+f"(c[3])
        : "r"(a[0]), "r"(a[1]), "r"(a[2]), "r"(a[3]), "r"(b[0]), "r"(b[1]));
}
__device__ __forceinline__ void cpa16(uint32_t dst, const void* src) {
    asm volatile("cp.async.cg.shared.global [%0], [%1], 16;" :: "r"(dst), "l"(src));
}
__device__ __forceinline__ void cpa_commit() {
    asm volatile("cp.async.commit_group;" ::: "memory");
}
template<int N>
__device__ __forceinline__ void cpa_wait() {
    asm volatile("cp.async.wait_group %0;" :: "n"(N) : "memory");
}

// ---------------- warp-mma tf32 GEMM, 2-stage cp.async pipeline ----------------
// C[m][n] = sum_k A[m][k]*W[n][k] + bias[n]
// Block 128x96, 8 warps (4m x 2n), warp tile 32x48, BK=32, K=192 (6 slabs).
template<int NOUT>
__global__ __launch_bounds__(256) void gemm_mma(
    const float* __restrict__ A, const float* __restrict__ W,
    const float* __restrict__ bias, float* __restrict__ C)
{
    extern __shared__ __align__(16) float sm[];
    float* Abuf = sm;                       // 2 * 128*36
    float* Bbuf = sm + 2 * 128 * 36;        // 2 *  96*36
    const uint32_t AbufS = smem_u32(Abuf);
    const uint32_t BbufS = smem_u32(Bbuf);

    const int t    = threadIdx.x;
    const int wid  = t >> 5;
    const int lane = t & 31;
    const int bm   = blockIdx.y * 128;
    const int bn   = blockIdx.x * 96;
    const int m0   = (wid >> 1) * 32;
    const int n0   = (wid & 1) * 48;
    const int gr   = lane >> 2;
    const int gc   = lane & 3;

    // staging coords (per thread): A 4 chunks, B 3 chunks
    const int ar = t >> 3 << 0;          // base handled in loop
    float acc[2][6][4];
#pragma unroll
    for (int i = 0; i < 2; ++i)
#pragma unroll
        for (int j = 0; j < 6; ++j)
#pragma unroll
            for (int r = 0; r < 4; ++r) acc[i][j][r] = 0.f;
    (void)ar;

    auto stage = [&](int slab, int buf) {
        const int k0 = slab * 32;
#pragma unroll
        for (int p = 0; p < 4; ++p) {
            int ci = t + p * 256;
            int r = ci >> 3, c = ci & 7;
            cpa16(AbufS + (uint32_t)(buf * 4608 + r * 36 + c * 4) * 4,
                  A + (size_t)(bm + r) * CDIM + k0 + c * 4);
        }
#pragma unroll
        for (int p = 0; p < 3; ++p) {
            int ci = t + p * 256;
            int r = ci >> 3, c = ci & 7;
            cpa16(BbufS + (uint32_t)(buf * 3456 + r * 36 + c * 4) * 4,
                  W + (size_t)(bn + r) * CDIM + k0 + c * 4);
        }
        cpa_commit();
    };

    stage(0, 0);

    for (int s = 0; s < 6; ++s) {
        const int buf = s & 1;
        if (s + 1 < 6) stage(s + 1, buf ^ 1);
        if (s + 1 < 6) cpa_wait<1>(); else cpa_wait<0>();
        __syncthreads();

        const float* As = Abuf + buf * 4608;
        const float* Bs = Bbuf + buf * 3456;
#pragma unroll
        for (int ks4 = 0; ks4 < 4; ++ks4) {
            const int kk = ks4 * 8;
            uint32_t af[2][4], bf[6][2];
#pragma unroll
            for (int mi = 0; mi < 2; ++mi) {
                int rb = m0 + mi * 16 + gr;
                af[mi][0] = __float_as_uint(As[rb * 36 + kk + gc]);
                af[mi][1] = __float_as_uint(As[(rb + 8) * 36 + kk + gc]);
                af[mi][2] = __float_as_uint(As[rb * 36 + kk + gc + 4]);
                af[mi][3] = __float_as_uint(As[(rb + 8) * 36 + kk + gc + 4]);
            }
#pragma unroll
            for (int ni = 0; ni < 6; ++ni) {
                int nb = n0 + ni * 8 + gr;
                bf[ni][0] = __float_as_uint(Bs[nb * 36 + kk + gc]);
                bf[ni][1] = __float_as_uint(Bs[nb * 36 + kk + gc + 4]);
            }
#pragma unroll
            for (int mi = 0; mi < 2; ++mi)
#pragma unroll
                for (int ni = 0; ni < 6; ++ni)
                    mma_tf32(acc[mi][ni], af[mi], bf[ni]);
        }
        __syncthreads();
    }

#pragma unroll
    for (int mi = 0; mi < 2; ++mi) {
        int mr = bm + m0 + mi * 16 + gr;
#pragma unroll
        for (int ni = 0; ni < 6; ++ni) {
            int nc = bn + n0 + ni * 8 + gc * 2;
            float2 bv = __ldg((const float2*)(bias + nc));
            float2 o0 = {acc[mi][ni][0] + bv.x, acc[mi][ni][1] + bv.y};
            float2 o1 = {acc[mi][ni][2] + bv.x, acc[mi][ni][3] + bv.y};
            *(float2*)(C + (size_t)mr * NOUT + nc)       = o0;
            *(float2*)(C + (size_t)(mr + 8) * NOUT + nc) = o1;
        }
    }
}

// ---------------- tensor-core window attention ----------------
// One block (128 thr, 4 warps) per (window, head). Warp w owns S rows [16w,16w+16).
__global__ __launch_bounds__(128) void win_attn(const float* __restrict__ bias)
{
    __shared__ float qs[64][36];    // [tok][d], q*scale
    __shared__ float kk_s[64][36];  // [tok][d]
    __shared__ float vT[32][68];    // [d][tok]
    __shared__ float ps[64][68];    // softmax probs

    const int pair = blockIdx.x;
    const int head = pair % NHEADS;
    const int win  = pair / NHEADS;
    const int b  = win >> 10;
    const int wy = (win >> 5) & 31;
    const int wx = win & 31;

    const int t    = threadIdx.x;
    const int wid  = t >> 5;
    const int lane = t & 31;
    const int gr   = lane >> 2;
    const int gc   = lane & 3;
    const float scale = 0.17677669529663687f;

    // gather (coalesced 128B per warp-row)
#pragma unroll
    for (int i = 0; i < 16; ++i) {
        int idx = t + i * 128;
        int p = idx >> 5;
        int d = idx & 31;
        int h = wy * 8 + (p >> 3);
        int w = wx * 8 + (p & 7);
        int tok = b * 65536 + h * 256 + w;
        const float* base = g_qkv + (size_t)tok * QKVN + head * 32 + d;
        qs[p][d]   = to_tf32(base[0] * scale);
        kk_s[p][d] = to_tf32(base[CDIM]);
        vT[d][p]   = to_tf32(base[2 * CDIM]);
    }
    __syncthreads();

    // S = q @ k^T  (warp: 16 rows x 64 cols), m16n8k8 x (1m x 8n x 4k)
    const int m0 = wid * 16;
    float s[8][4];
#pragma unroll
    for (int ni = 0; ni < 8; ++ni)
#pragma unroll
        for (int r = 0; r < 4; ++r) s[ni][r] = 0.f;

#pragma unroll
    for (int ks4 = 0; ks4 < 4; ++ks4) {
        const int kc = ks4 * 8;
        uint32_t a[4];
        a[0] = __float_as_uint(qs[m0 + gr][kc + gc]);
        a[1] = __float_as_uint(qs[m0 + gr + 8][kc + gc]);
        a[2] = __float_as_uint(qs[m0 + gr][kc + gc + 4]);
        a[3] = __float_as_uint(qs[m0 + gr + 8][kc + gc + 4]);
#pragma unroll
        for (int ni = 0; ni < 8; ++ni) {
            uint32_t bfr[2];
            bfr[0] = __float_as_uint(kk_s[ni * 8 + gr][kc + gc]);
            bfr[1] = __float_as_uint(kk_s[ni * 8 + gr][kc + gc + 4]);
            mma_tf32(s[ni], a, bfr);
        }
    }

    // bias add + register softmax (rows r0 = m0+gr, r1 = r0+8)
    const int r0 = m0 + gr;
    const int r1 = r0 + 8;
    const float* bp = bias + head * 4096;
    float mx0 = -1e30f, mx1 = -1e30f;
#pragma unroll
    for (int ni = 0; ni < 8; ++ni) {
        float2 b0 = __ldg((const float2*)(bp + r0 * 64 + ni * 8 + gc * 2));
        float2 b1 = __ldg((const float2*)(bp + r1 * 64 + ni * 8 + gc * 2));
        s[ni][0] += b0.x; s[ni][1] += b0.y;
        s[ni][2] += b1.x; s[ni][3] += b1.y;
        mx0 = fmaxf(mx0, fmaxf(s[ni][0], s[ni][1]));
        mx1 = fmaxf(mx1, fmaxf(s[ni][2], s[ni][3]));
    }
    mx0 = fmaxf(mx0, __shfl_xor_sync(0xffffffffu, mx0, 1));
    mx0 = fmaxf(mx0, __shfl_xor_sync(0xffffffffu, mx0, 2));
    mx1 = fmaxf(mx1, __shfl_xor_sync(0xffffffffu, mx1, 1));
    mx1 = fmaxf(mx1, __shfl_xor_sync(0xffffffffu, mx1, 2));

    float sum0 = 0.f, sum1 = 0.f;
#pragma unroll
    for (int ni = 0; ni < 8; ++ni) {
        s[ni][0] = __expf(s[ni][0] - mx0);
        s[ni][1] = __expf(s[ni][1] - mx0);
        s[ni][2] = __expf(s[ni][2] - mx1);
        s[ni][3] = __expf(s[ni][3] - mx1);
        sum0 += s[ni][0] + s[ni][1];
        sum1 += s[ni][2] + s[ni][3];
    }
    sum0 += __shfl_xor_sync(0xffffffffu, sum0, 1);
    sum0 += __shfl_xor_sync(0xffffffffu, sum0, 2);
    sum1 += __shfl_xor_sync(0xffffffffu, sum1, 1);
    sum1 += __shfl_xor_sync(0xffffffffu, sum1, 2);
    const float inv0 = 1.f / sum0;
    const float inv1 = 1.f / sum1;

#pragma unroll
    for (int ni = 0; ni < 8; ++ni) {
        float2 p0 = {to_tf32(s[ni][0] * inv0), to_tf32(s[ni][1] * inv0)};
        float2 p1 = {to_tf32(s[ni][2] * inv1), to_tf32(s[ni][3] * inv1)};
        *(float2*)&ps[r0][ni * 8 + gc * 2] = p0;
        *(float2*)&ps[r1][ni * 8 + gc * 2] = p1;
    }
    __syncwarp();

    // O = P @ V  (warp: 16 rows x 32 d), m16n8k8 x (1m x 4n x 8k)
    float o[4][4];
#pragma unroll
    for (int ni = 0; ni < 4; ++ni)
#pragma unroll
        for (int r = 0; r < 4; ++r) o[ni][r] = 0.f;

#pragma unroll
    for (int ks8 = 0; ks8 < 8; ++ks8) {
        const int kc = ks8 * 8;
        uint32_t a[4];
        a[0] = __float_as_uint(ps[m0 + gr][kc + gc]);
        a[1] = __float_as_uint(ps[m0 + gr + 8][kc + gc]);
        a[2] = __float_as_uint(ps[m0 + gr][kc + gc + 4]);
        a[3] = __float_as_uint(ps[m0 + gr + 8][kc + gc + 4]);
#pragma unroll
        for (int ni = 0; ni < 4; ++ni) {
            uint32_t bfr[2];
            bfr[0] = __float_as_uint(vT[ni * 8 + gr][kc + gc]);
            bfr[1] = __float_as_uint(vT[ni * 8 + gr][kc + gc + 4]);
            mma_tf32(o[ni], a, bfr);
        }
    }

    // scatter O: rows r0/r1, col d = ni*8 + 2*gc
    {
        int h0 = wy * 8 + (r0 >> 3), w0 = wx * 8 + (r0 & 7);
        int h1 = wy * 8 + (r1 >> 3), w1 = wx * 8 + (r1 & 7);
        size_t tok0 = (size_t)(b * 65536 + h0 * 256 + w0) * CDIM + head * 32;
        size_t tok1 = (size_t)(b * 65536 + h1 * 256 + w1) * CDIM + head * 32;
#pragma unroll
        for (int ni = 0; ni < 4; ++ni) {
            int d = ni * 8 + gc * 2;
            *(float2*)(g_att + tok0 + d) = make_float2(o[ni][0], o[ni][1]);
            *(float2*)(g_att + tok1 + d) = make_float2(o[ni][2], o[ni][3]);
        }
    }
}

extern "C" void kernel_launch(void* const* d_in, const int* in_sizes, int n_in,
                              void* d_out, int out_size)
{
    const float* x      = (const float*)d_in[0];
    const float* qkv_w  = (const float*)d_in[1];
    const float* qkv_b  = (const float*)d_in[2];
    const float* proj_w = (const float*)d_in[3];
    const float* proj_b = (const float*)d_in[4];
    const float* bias   = (const float*)d_in[5];
    float* out = (float*)d_out;

    float *qkv_p = nullptr, *att_p = nullptr;
    cudaGetSymbolAddress((void**)&qkv_p, g_qkv);
    cudaGetSymbolAddress((void**)&att_p, g_att);

    const int smem_bytes = (2 * 128 * 36 + 2 * 96 * 36) * 4;   // 64512
    cudaFuncSetAttribute(gemm_mma<QKVN>, cudaFuncAttributeMaxDynamicSharedMemorySize, smem_bytes);
    cudaFuncSetAttribute(gemm_mma<CDIM>, cudaFuncAttributeMaxDynamicSharedMemorySize, smem_bytes);

    dim3 g1(QKVN / 96, TOKENS / 128);
    gemm_mma<QKVN><<<g1, 256, smem_bytes>>>(x, qkv_w, qkv_b, qkv_p);

    win_attn<<<NWINS * NHEADS, 128>>>(bias);

    dim3 g3(CDIM / 96, TOKENS / 128);
    gemm_mma<CDIM><<<g3, 256, smem_bytes>>>(att_p, proj_w, proj_b, out);
}